// round 1
// baseline (speedup 1.0000x reference)
#include <cuda_runtime.h>
#include <math.h>

// Problem constants
#define B_DIM 4
#define N_DIM 8192
#define M_DIM 8192
#define C_DIM 512
#define H_DIM 8
#define D_DIM 64
#define BH    (B_DIM * H_DIM)     // 32
#define ROWS  (B_DIM * N_DIM)     // 32768 rows for x-side
#define CH      64                 // rows of M per kv-partial chunk
#define NCHUNK  (M_DIM / CH)       // 128

// Scratch (device globals; no allocation in kernel_launch)
__device__ float g_Q  [(size_t)B_DIM * N_DIM * C_DIM];
__device__ float g_K  [(size_t)B_DIM * M_DIM * C_DIM];
__device__ float g_V  [(size_t)B_DIM * M_DIM * C_DIM];
__device__ float g_ATT[(size_t)B_DIM * N_DIM * C_DIM];
__device__ float g_kvp [(size_t)BH * NCHUNK * D_DIM * D_DIM];
__device__ float g_ksp [(size_t)BH * NCHUNK * D_DIM];
__device__ float g_kv  [BH * D_DIM * D_DIM];
__device__ float g_ksum[BH * D_DIM];

// ---------------------------------------------------------------------------
// GEMM: C[32768 x 512] = A[32768 x 512] @ Bm[512 x 512] + bias[512]
// 128x128 tile, BK=8, 256 threads, 8x8 per thread.
// ---------------------------------------------------------------------------
__global__ __launch_bounds__(256) void gemm_bias_k(
    const float* __restrict__ A, const float* __restrict__ Bm,
    const float* __restrict__ bias, float* __restrict__ C)
{
    __shared__ float As[8][128];
    __shared__ float Bs[8][128];
    const int tid = threadIdx.x;
    const int bx = blockIdx.x;   // 0..3 over N
    const int by = blockIdx.y;   // 0..255 over M

    const float* Ab = A + (size_t)by * 128 * C_DIM;
    const float* Bb = Bm + bx * 128;

    const int arow = tid >> 1;             // 0..127
    const int acol = (tid & 1) << 2;       // 0 or 4
    const int brow = tid >> 5;             // 0..7
    const int bcol = (tid & 31) << 2;      // 0..124
    const int tx = (tid & 15) << 3;        // col offset 0..120
    const int ty = (tid >> 4) << 3;        // row offset 0..120

    float acc[8][8] = {};

    for (int k0 = 0; k0 < C_DIM; k0 += 8) {
        float4 a4 = *(const float4*)(Ab + (size_t)arow * C_DIM + k0 + acol);
        As[acol + 0][arow] = a4.x;
        As[acol + 1][arow] = a4.y;
        As[acol + 2][arow] = a4.z;
        As[acol + 3][arow] = a4.w;
        *(float4*)&Bs[brow][bcol] =
            *(const float4*)(Bb + (size_t)(k0 + brow) * C_DIM + bcol);
        __syncthreads();
#pragma unroll
        for (int k = 0; k < 8; k++) {
            float af[8], bf[8];
            *(float4*)&af[0] = *(const float4*)&As[k][ty];
            *(float4*)&af[4] = *(const float4*)&As[k][ty + 4];
            *(float4*)&bf[0] = *(const float4*)&Bs[k][tx];
            *(float4*)&bf[4] = *(const float4*)&Bs[k][tx + 4];
#pragma unroll
            for (int i = 0; i < 8; i++)
#pragma unroll
                for (int j = 0; j < 8; j++)
                    acc[i][j] += af[i] * bf[j];
        }
        __syncthreads();
    }

    // Epilogue: add bias, store
    float bv[8];
#pragma unroll
    for (int j = 0; j < 8; j++) bv[j] = __ldg(bias + bx * 128 + tx + j);
#pragma unroll
    for (int i = 0; i < 8; i++) {
        size_t row = (size_t)by * 128 + ty + i;
        float* Crow = C + row * C_DIM + bx * 128 + tx;
        float4 o0, o1;
        o0.x = acc[i][0] + bv[0]; o0.y = acc[i][1] + bv[1];
        o0.z = acc[i][2] + bv[2]; o0.w = acc[i][3] + bv[3];
        o1.x = acc[i][4] + bv[4]; o1.y = acc[i][5] + bv[5];
        o1.z = acc[i][6] + bv[6]; o1.w = acc[i][7] + bv[7];
        *(float4*)(Crow)     = o0;
        *(float4*)(Crow + 4) = o1;
    }
}

// ---------------------------------------------------------------------------
// Softmax over each 64-wide head slice of every row. In-place.
// One warp per (row, head). X shape: (rows, 512).
// ---------------------------------------------------------------------------
__global__ __launch_bounds__(256) void softmax64_k(float* __restrict__ X)
{
    int gw   = (blockIdx.x * blockDim.x + threadIdx.x) >> 5;  // global warp id
    int lane = threadIdx.x & 31;
    int r = gw >> 3;
    int h = gw & 7;
    float* p = X + (size_t)r * C_DIM + h * D_DIM;
    float v0 = p[lane], v1 = p[lane + 32];
    float mx = fmaxf(v0, v1);
#pragma unroll
    for (int o = 16; o; o >>= 1) mx = fmaxf(mx, __shfl_xor_sync(~0u, mx, o));
    float e0 = expf(v0 - mx), e1 = expf(v1 - mx);
    float s = e0 + e1;
#pragma unroll
    for (int o = 16; o; o >>= 1) s += __shfl_xor_sync(~0u, s, o);
    float inv = 1.0f / s;
    p[lane]      = e0 * inv;
    p[lane + 32] = e1 * inv;
}

// ---------------------------------------------------------------------------
// kv partials: for (bh, chunk) accumulate K^T V over CH rows of m, plus
// column-sum of K. Deterministic two-stage (no atomics).
// ---------------------------------------------------------------------------
__global__ __launch_bounds__(256) void kv_partial_k()
{
    const int bh = blockIdx.x, chunk = blockIdx.y;
    const int b = bh >> 3, h = bh & 7;
    __shared__ float Ks[CH][64];
    __shared__ float Vs[CH][64];
    const int tid = threadIdx.x;
    const float* Kb = g_K + ((size_t)b * M_DIM + chunk * CH) * C_DIM + h * D_DIM;
    const float* Vb = g_V + ((size_t)b * M_DIM + chunk * CH) * C_DIM + h * D_DIM;

    for (int i = tid; i < CH * 16; i += 256) {
        int m = i >> 4, c4 = (i & 15) << 2;
        *(float4*)&Ks[m][c4] = *(const float4*)(Kb + (size_t)m * C_DIM + c4);
        *(float4*)&Vs[m][c4] = *(const float4*)(Vb + (size_t)m * C_DIM + c4);
    }
    __syncthreads();

    const int d0 = (tid >> 4) << 2;   // 0..60
    const int e0 = (tid & 15) << 2;   // 0..60
    float acc[4][4] = {};
    for (int m = 0; m < CH; m++) {
        float4 kd = *(const float4*)&Ks[m][d0];
        float4 ve = *(const float4*)&Vs[m][e0];
        float kf[4] = {kd.x, kd.y, kd.z, kd.w};
        float vf[4] = {ve.x, ve.y, ve.z, ve.w};
#pragma unroll
        for (int i = 0; i < 4; i++)
#pragma unroll
            for (int j = 0; j < 4; j++)
                acc[i][j] += kf[i] * vf[j];
    }
    float* dst = g_kvp + ((size_t)bh * NCHUNK + chunk) * (D_DIM * D_DIM);
#pragma unroll
    for (int i = 0; i < 4; i++) {
        float4 o = make_float4(acc[i][0], acc[i][1], acc[i][2], acc[i][3]);
        *(float4*)(dst + (d0 + i) * D_DIM + e0) = o;
    }
    if (tid < 64) {
        float s = 0.f;
        for (int m = 0; m < CH; m++) s += Ks[m][tid];
        g_ksp[((size_t)bh * NCHUNK + chunk) * D_DIM + tid] = s;
    }
}

// Reduce partials into g_kv, g_ksum. grid (BH, 16), 256 threads.
__global__ __launch_bounds__(256) void kv_reduce_k()
{
    const int bh = blockIdx.x;
    const int i = blockIdx.y * 256 + threadIdx.x;   // 0..4095
    const float* src = g_kvp + (size_t)bh * NCHUNK * (D_DIM * D_DIM) + i;
    float s = 0.f;
    for (int c = 0; c < NCHUNK; c++) s += src[(size_t)c * (D_DIM * D_DIM)];
    g_kv[bh * (D_DIM * D_DIM) + i] = s;
    if (blockIdx.y == 0 && threadIdx.x < 64) {
        const float* sp = g_ksp + (size_t)bh * NCHUNK * D_DIM + threadIdx.x;
        float t = 0.f;
        for (int c = 0; c < NCHUNK; c++) t += sp[c * D_DIM];
        g_ksum[bh * D_DIM + threadIdx.x] = t;
    }
}

// ---------------------------------------------------------------------------
// Attention core: out = q @ kv / denom + q, per (b,h). 64 q-rows per block.
// grid (BH, N/64), 256 threads (4 threads per row, 16 cols each).
// ---------------------------------------------------------------------------
__global__ __launch_bounds__(256) void attn_k()
{
    const int bh = blockIdx.x;
    const int b = bh >> 3, h = bh & 7;
    const int n0 = blockIdx.y * 64;
    __shared__ float kvs[64][64];
    __shared__ float ksums[64];
    __shared__ float qs[64][68];   // padded: avoid 8-way bank conflict on column reads
    const int tid = threadIdx.x;

    {
        const float* kvsrc = g_kv + bh * (D_DIM * D_DIM);
        for (int i = tid; i < 1024; i += 256) {
            int d = i >> 4, c4 = (i & 15) << 2;
            *(float4*)&kvs[d][c4] = *(const float4*)(kvsrc + d * 64 + c4);
        }
        const float* Qb = g_Q + ((size_t)b * N_DIM + n0) * C_DIM + h * D_DIM;
        for (int i = tid; i < 1024; i += 256) {
            int m = i >> 4, c4 = (i & 15) << 2;
            *(float4*)&qs[m][c4] = *(const float4*)(Qb + (size_t)m * C_DIM + c4);
        }
        if (tid < 64) ksums[tid] = g_ksum[bh * D_DIM + tid];
    }
    __syncthreads();

    const int r  = tid >> 2;          // 0..63
    const int e0 = (tid & 3) << 4;    // 0,16,32,48

    float denom = 0.f;
#pragma unroll
    for (int d = 0; d < 64; d++) denom += qs[r][d] * ksums[d];
    denom = fmaxf(denom, 1e-6f);
    const float inv = 1.0f / denom;

    float acc[16] = {};
    for (int d = 0; d < 64; d++) {
        float qd = qs[r][d];
#pragma unroll
        for (int j = 0; j < 16; j++) acc[j] += qd * kvs[d][e0 + j];
    }

    float* Ob = g_ATT + ((size_t)b * N_DIM + n0 + r) * C_DIM + h * D_DIM + e0;
#pragma unroll
    for (int j = 0; j < 16; j += 4) {
        float4 o;
        o.x = acc[j + 0] * inv + qs[r][e0 + j + 0];
        o.y = acc[j + 1] * inv + qs[r][e0 + j + 1];
        o.z = acc[j + 2] * inv + qs[r][e0 + j + 2];
        o.w = acc[j + 3] * inv + qs[r][e0 + j + 3];
        *(float4*)(Ob + j) = o;
    }
}

// ---------------------------------------------------------------------------
// Launch
// ---------------------------------------------------------------------------
static float* sym_addr(const void* s)
{
    void* p = nullptr;
    cudaGetSymbolAddress(&p, s);
    return (float*)p;
}

extern "C" void kernel_launch(void* const* d_in, const int* in_sizes, int n_in,
                              void* d_out, int out_size)
{
    const float* x  = (const float*)d_in[0];
    const float* y  = (const float*)d_in[1];
    const float* Wq = (const float*)d_in[2];
    const float* bq = (const float*)d_in[3];
    const float* Wk = (const float*)d_in[4];
    const float* bk = (const float*)d_in[5];
    const float* Wv = (const float*)d_in[6];
    const float* bv = (const float*)d_in[7];
    const float* Wp = (const float*)d_in[8];
    const float* bp = (const float*)d_in[9];
    float* out = (float*)d_out;

    float* Q   = sym_addr(g_Q);
    float* K   = sym_addr(g_K);
    float* V   = sym_addr(g_V);
    float* ATT = sym_addr(g_ATT);

    dim3 ggrid(C_DIM / 128, ROWS / 128);   // (4, 256)
    dim3 gblk(256);

    gemm_bias_k<<<ggrid, gblk>>>(x, Wq, bq, Q);
    gemm_bias_k<<<ggrid, gblk>>>(y, Wk, bk, K);
    gemm_bias_k<<<ggrid, gblk>>>(y, Wv, bv, V);

    softmax64_k<<<ROWS, 256>>>(Q);   // 8 warps/block -> one (row,head) per warp
    softmax64_k<<<ROWS, 256>>>(K);

    kv_partial_k<<<dim3(BH, NCHUNK), 256>>>();
    kv_reduce_k<<<dim3(BH, 16), 256>>>();

    attn_k<<<dim3(BH, N_DIM / 64), 256>>>();

    gemm_bias_k<<<ggrid, gblk>>>(ATT, Wp, bp, out);
}

// round 4
// speedup vs baseline: 2.4138x; 2.4138x over previous
#include <cuda_runtime.h>
#include <cstdint>
#include <math.h>

// Problem constants
#define B_DIM 4
#define N_DIM 8192
#define M_DIM 8192
#define C_DIM 512
#define H_DIM 8
#define D_DIM 64
#define BH    (B_DIM * H_DIM)     // 32
#define ROWS  (B_DIM * N_DIM)     // 32768
#define CH      64
#define NCHUNK  (M_DIM / CH)      // 128

// ---------------------------------------------------------------------------
// Scratch (device globals; no allocation in kernel_launch)
// ---------------------------------------------------------------------------
__device__ float g_Q  [(size_t)B_DIM * N_DIM * C_DIM];
__device__ float g_K  [(size_t)B_DIM * M_DIM * C_DIM];
__device__ float g_V  [(size_t)B_DIM * M_DIM * C_DIM];
__device__ float g_ATT[(size_t)B_DIM * N_DIM * C_DIM];
__device__ float g_kvp [(size_t)BH * NCHUNK * D_DIM * D_DIM];
__device__ float g_ksp [(size_t)BH * NCHUNK * D_DIM];
__device__ float g_kv  [BH * D_DIM * D_DIM];
__device__ float g_ksum[BH * D_DIM];

// ---------------------------------------------------------------------------
// Helpers
// ---------------------------------------------------------------------------
__device__ __forceinline__ uint32_t smem_u32(const void* p) {
    uint32_t a;
    asm("{ .reg .u64 t; cvta.to.shared.u64 t, %1; cvt.u32.u64 %0, t; }"
        : "=r"(a) : "l"(p));
    return a;
}
__device__ __forceinline__ uint32_t tf32_bits(float x) {
    float r;
    asm("cvt.rna.tf32.f32 %0, %1;" : "=f"(r) : "f"(x));
    return __float_as_uint(r);
}
__device__ __forceinline__ void cp16(uint32_t dst, const void* src) {
    asm volatile("cp.async.cg.shared.global [%0], [%1], 16;" :: "r"(dst), "l"(src));
}
#define CP_COMMIT() asm volatile("cp.async.commit_group;" ::: "memory")

__device__ __forceinline__ void mma_tf32(
    float c[4], const uint32_t a[4], const uint32_t b[2])
{
    asm volatile(
        "mma.sync.aligned.m16n8k8.row.col.f32.tf32.tf32.f32 "
        "{%0,%1,%2,%3}, {%4,%5,%6,%7}, {%8,%9}, {%0,%1,%2,%3};"
        : "+f"(c[0]), "+f"(c[1]), "+f"(c[2]), "+f"(c[3])
        : "r"(a[0]), "r"(a[1]), "r"(a[2]), "r"(a[3]), "r"(b[0]), "r"(b[1]));
}

// ---------------------------------------------------------------------------
// GEMM: C[32768 x 512] = A[32768 x 512] @ W[512 x 512] + bias[512]
// mma.sync tf32, 128x128 block tile, BK=16, cp.async double buffer.
// 256 threads = 8 warps (2 m x 4 n), warp tile 64x32.
// A staged as [128 m][20 pad k]; W staged as [16 k][136 pad n].
// tf32 rounding (rna) applied to fragments in registers.
// ---------------------------------------------------------------------------
#define BK      16
#define A_PAD   20      // floats per m-row in smem
#define W_PAD   136     // floats per k-row in smem
#define A_STG   (128 * A_PAD)
#define W_STG   (BK * W_PAD)

__global__ __launch_bounds__(256, 2) void gemm_mma(
    const float* __restrict__ A, const float* __restrict__ W,
    const float* __restrict__ bias, float* __restrict__ Cw)
{
    __shared__ float sA[2][A_STG];
    __shared__ float sB[2][W_STG];

    const int tid = threadIdx.x;
    const int bx = blockIdx.x;   // 0..3   output col tile (128)
    const int by = blockIdx.y;   // 0..255 output row tile (128)

    const float* Ab = A + (size_t)by * 128 * C_DIM;
    const float* Wb = W + bx * 128;

    const uint32_t sA0 = smem_u32(&sA[0][0]);
    const uint32_t sA1 = smem_u32(&sA[1][0]);
    const uint32_t sB0 = smem_u32(&sB[0][0]);
    const uint32_t sB1 = smem_u32(&sB[1][0]);

    // ---- stage loader ----
    auto load_stage = [&](int stg) {
        const int buf = stg & 1;
        const int k0 = stg * BK;
        const uint32_t ab = buf ? sA1 : sA0;
        const uint32_t bb = buf ? sB1 : sB0;
        // A: 128 rows x 16 floats = 512 x 16B chunks; 2 per thread
#pragma unroll
        for (int q = 0; q < 2; q++) {
            const int c = tid + q * 256;
            const int row = c >> 2;            // 0..127
            const int cc = c & 3;              // 0..3
            cp16(ab + (uint32_t)(row * A_PAD + cc * 4) * 4u,
                 Ab + (size_t)row * C_DIM + k0 + cc * 4);
        }
        // W: 16 rows x 128 floats = 512 x 16B chunks; 2 per thread  (FIXED)
#pragma unroll
        for (int q = 0; q < 2; q++) {
            const int c = tid + q * 256;
            const int row = c >> 5;            // 0..15
            const int cc = c & 31;             // 0..31
            cp16(bb + (uint32_t)(row * W_PAD + cc * 4) * 4u,
                 Wb + (size_t)(k0 + row) * C_DIM + cc * 4);
        }
        CP_COMMIT();
    };

    const int wid  = tid >> 5;
    const int lane = tid & 31;
    const int wm = (wid >> 2) * 64;   // warp m-offset: 0 / 64
    const int wn = (wid & 3) * 32;    // warp n-offset: 0/32/64/96
    const int g  = lane >> 2;         // group id 0..7
    const int tg = lane & 3;          // thread-in-group

    float acc[4][4][4];               // [m-tile][n-tile][frag]
#pragma unroll
    for (int i = 0; i < 4; i++)
#pragma unroll
        for (int j = 0; j < 4; j++)
#pragma unroll
            for (int t = 0; t < 4; t++) acc[i][j][t] = 0.f;

    load_stage(0);
    load_stage(1);

    const int NS = C_DIM / BK;   // 32
    for (int i = 0; i < NS; i++) {
        if (i < NS - 2) asm volatile("cp.async.wait_group 1;" ::: "memory");
        else            asm volatile("cp.async.wait_group 0;" ::: "memory");
        __syncthreads();

        const float* a_s = sA[i & 1];
        const float* b_s = sB[i & 1];
#pragma unroll
        for (int kk = 0; kk < BK / 8; kk++) {
            const int k0 = kk * 8;
            uint32_t af[4][4];
#pragma unroll
            for (int mt = 0; mt < 4; mt++) {
                const int m = wm + mt * 16 + g;
                af[mt][0] = tf32_bits(a_s[m * A_PAD + k0 + tg]);
                af[mt][1] = tf32_bits(a_s[(m + 8) * A_PAD + k0 + tg]);
                af[mt][2] = tf32_bits(a_s[m * A_PAD + k0 + tg + 4]);
                af[mt][3] = tf32_bits(a_s[(m + 8) * A_PAD + k0 + tg + 4]);
            }
            uint32_t bf[4][2];
#pragma unroll
            for (int nt = 0; nt < 4; nt++) {
                const int n = wn + nt * 8 + g;
                bf[nt][0] = tf32_bits(b_s[(k0 + tg) * W_PAD + n]);
                bf[nt][1] = tf32_bits(b_s[(k0 + tg + 4) * W_PAD + n]);
            }
#pragma unroll
            for (int mt = 0; mt < 4; mt++)
#pragma unroll
                for (int nt = 0; nt < 4; nt++)
                    mma_tf32(acc[mt][nt], af[mt], bf[nt]);
        }
        __syncthreads();
        if (i + 2 < NS) load_stage(i + 2);
    }

    // ---- epilogue: bias + store (fp32) ----
#pragma unroll
    for (int nt = 0; nt < 4; nt++) {
        const int col = bx * 128 + wn + nt * 8 + tg * 2;
        const float b0 = __ldg(bias + col);
        const float b1 = __ldg(bias + col + 1);
#pragma unroll
        for (int mt = 0; mt < 4; mt++) {
            const size_t r0 = (size_t)by * 128 + wm + mt * 16 + g;
            float2 o0 = make_float2(acc[mt][nt][0] + b0, acc[mt][nt][1] + b1);
            float2 o1 = make_float2(acc[mt][nt][2] + b0, acc[mt][nt][3] + b1);
            *(float2*)(Cw + r0 * C_DIM + col)       = o0;
            *(float2*)(Cw + (r0 + 8) * C_DIM + col) = o1;
        }
    }
}

// ---------------------------------------------------------------------------
// Softmax over each 64-wide head slice. One warp per (row, head).
// ---------------------------------------------------------------------------
__global__ __launch_bounds__(256) void softmax64_k(float* __restrict__ X)
{
    int gw   = (blockIdx.x * blockDim.x + threadIdx.x) >> 5;
    int lane = threadIdx.x & 31;
    int r = gw >> 3;
    int h = gw & 7;
    float* p = X + (size_t)r * C_DIM + h * D_DIM;
    float v0 = p[lane], v1 = p[lane + 32];
    float mx = fmaxf(v0, v1);
#pragma unroll
    for (int o = 16; o; o >>= 1) mx = fmaxf(mx, __shfl_xor_sync(~0u, mx, o));
    float e0 = expf(v0 - mx), e1 = expf(v1 - mx);
    float s = e0 + e1;
#pragma unroll
    for (int o = 16; o; o >>= 1) s += __shfl_xor_sync(~0u, s, o);
    float inv = 1.0f / s;
    p[lane]      = e0 * inv;
    p[lane + 32] = e1 * inv;
}

// ---------------------------------------------------------------------------
// kv partials + reduce (deterministic, fp32)
// ---------------------------------------------------------------------------
__global__ __launch_bounds__(256) void kv_partial_k()
{
    const int bh = blockIdx.x, chunk = blockIdx.y;
    const int b = bh >> 3, h = bh & 7;
    __shared__ float Ks[CH][64];
    __shared__ float Vs[CH][64];
    const int tid = threadIdx.x;
    const float* Kb = g_K + ((size_t)b * M_DIM + chunk * CH) * C_DIM + h * D_DIM;
    const float* Vb = g_V + ((size_t)b * M_DIM + chunk * CH) * C_DIM + h * D_DIM;

    for (int i = tid; i < CH * 16; i += 256) {
        int m = i >> 4, c4 = (i & 15) << 2;
        *(float4*)&Ks[m][c4] = *(const float4*)(Kb + (size_t)m * C_DIM + c4);
        *(float4*)&Vs[m][c4] = *(const float4*)(Vb + (size_t)m * C_DIM + c4);
    }
    __syncthreads();

    const int d0 = (tid >> 4) << 2;
    const int e0 = (tid & 15) << 2;
    float acc[4][4] = {};
    for (int m = 0; m < CH; m++) {
        float4 kd = *(const float4*)&Ks[m][d0];
        float4 ve = *(const float4*)&Vs[m][e0];
        float kf[4] = {kd.x, kd.y, kd.z, kd.w};
        float vf[4] = {ve.x, ve.y, ve.z, ve.w};
#pragma unroll
        for (int i = 0; i < 4; i++)
#pragma unroll
            for (int j = 0; j < 4; j++)
                acc[i][j] += kf[i] * vf[j];
    }
    float* dst = g_kvp + ((size_t)bh * NCHUNK + chunk) * (D_DIM * D_DIM);
#pragma unroll
    for (int i = 0; i < 4; i++) {
        float4 o = make_float4(acc[i][0], acc[i][1], acc[i][2], acc[i][3]);
        *(float4*)(dst + (d0 + i) * D_DIM + e0) = o;
    }
    if (tid < 64) {
        float s = 0.f;
        for (int m = 0; m < CH; m++) s += Ks[m][tid];
        g_ksp[((size_t)bh * NCHUNK + chunk) * D_DIM + tid] = s;
    }
}

__global__ __launch_bounds__(256) void kv_reduce_k()
{
    const int bh = blockIdx.x;
    const int i = blockIdx.y * 256 + threadIdx.x;
    const float* src = g_kvp + (size_t)bh * NCHUNK * (D_DIM * D_DIM) + i;
    float s = 0.f;
    for (int c = 0; c < NCHUNK; c++) s += src[(size_t)c * (D_DIM * D_DIM)];
    g_kv[bh * (D_DIM * D_DIM) + i] = s;
    if (blockIdx.y == 0 && threadIdx.x < 64) {
        const float* sp = g_ksp + (size_t)bh * NCHUNK * D_DIM + threadIdx.x;
        float t = 0.f;
        for (int c = 0; c < NCHUNK; c++) t += sp[c * D_DIM];
        g_ksum[bh * D_DIM + threadIdx.x] = t;
    }
}

// ---------------------------------------------------------------------------
// Attention core: ATT = q @ kv / denom + q
// ---------------------------------------------------------------------------
__global__ __launch_bounds__(256) void attn_k()
{
    const int bh = blockIdx.x;
    const int b = bh >> 3, h = bh & 7;
    const int n0 = blockIdx.y * 64;
    __shared__ float kvs[64][64];
    __shared__ float ksums[64];
    __shared__ float qs[64][68];
    const int tid = threadIdx.x;

    {
        const float* kvsrc = g_kv + bh * (D_DIM * D_DIM);
        for (int i = tid; i < 1024; i += 256) {
            int d = i >> 4, c4 = (i & 15) << 2;
            *(float4*)&kvs[d][c4] = *(const float4*)(kvsrc + d * 64 + c4);
        }
        const float* Qb = g_Q + ((size_t)b * N_DIM + n0) * C_DIM + h * D_DIM;
        for (int i = tid; i < 1024; i += 256) {
            int m = i >> 4, c4 = (i & 15) << 2;
            *(float4*)&qs[m][c4] = *(const float4*)(Qb + (size_t)m * C_DIM + c4);
        }
        if (tid < 64) ksums[tid] = g_ksum[bh * D_DIM + tid];
    }
    __syncthreads();

    const int r  = tid >> 2;
    const int e0 = (tid & 3) << 4;

    float denom = 0.f;
#pragma unroll
    for (int d = 0; d < 64; d++) denom += qs[r][d] * ksums[d];
    denom = fmaxf(denom, 1e-6f);
    const float inv = 1.0f / denom;

    float acc[16] = {};
    for (int d = 0; d < 64; d++) {
        float qd = qs[r][d];
#pragma unroll
        for (int j = 0; j < 16; j++) acc[j] += qd * kvs[d][e0 + j];
    }

    float* Ob = g_ATT + ((size_t)b * N_DIM + n0 + r) * C_DIM + h * D_DIM + e0;
#pragma unroll
    for (int j = 0; j < 16; j += 4) {
        float4 o;
        o.x = acc[j + 0] * inv + qs[r][e0 + j + 0];
        o.y = acc[j + 1] * inv + qs[r][e0 + j + 1];
        o.z = acc[j + 2] * inv + qs[r][e0 + j + 2];
        o.w = acc[j + 3] * inv + qs[r][e0 + j + 3];
        *(float4*)(Ob + j) = o;
    }
}

// ---------------------------------------------------------------------------
// Launch
// ---------------------------------------------------------------------------
static float* sym_addr(const void* s)
{
    void* p = nullptr;
    cudaGetSymbolAddress(&p, s);
    return (float*)p;
}

extern "C" void kernel_launch(void* const* d_in, const int* in_sizes, int n_in,
                              void* d_out, int out_size)
{
    const float* x  = (const float*)d_in[0];
    const float* y  = (const float*)d_in[1];
    const float* Wq = (const float*)d_in[2];
    const float* bq = (const float*)d_in[3];
    const float* Wk = (const float*)d_in[4];
    const float* bk = (const float*)d_in[5];
    const float* Wv = (const float*)d_in[6];
    const float* bv = (const float*)d_in[7];
    const float* Wp = (const float*)d_in[8];
    const float* bp = (const float*)d_in[9];
    float* out = (float*)d_out;

    float* Q   = sym_addr(g_Q);
    float* K   = sym_addr(g_K);
    float* V   = sym_addr(g_V);
    float* ATT = sym_addr(g_ATT);

    dim3 ggrid(C_DIM / 128, ROWS / 128);   // (4, 256)

    gemm_mma<<<ggrid, 256>>>(x, Wq, bq, Q);
    gemm_mma<<<ggrid, 256>>>(y, Wk, bk, K);
    gemm_mma<<<ggrid, 256>>>(y, Wv, bv, V);

    softmax64_k<<<ROWS, 256>>>(Q);
    softmax64_k<<<ROWS, 256>>>(K);

    kv_partial_k<<<dim3(BH, NCHUNK), 256>>>();
    kv_reduce_k<<<dim3(BH, 16), 256>>>();

    attn_k<<<dim3(BH, N_DIM / 64), 256>>>();

    gemm_mma<<<ggrid, 256>>>(ATT, Wp, bp, out);
}

// round 9
// speedup vs baseline: 2.5268x; 1.0468x over previous
#include <cuda_runtime.h>
#include <cstdint>
#include <math.h>

// Problem constants
#define B_DIM 4
#define N_DIM 8192
#define M_DIM 8192
#define C_DIM 512
#define H_DIM 8
#define D_DIM 64
#define BH    (B_DIM * H_DIM)     // 32
#define ROWS  (B_DIM * N_DIM)     // 32768
#define CH      64
#define NCHUNK  (M_DIM / CH)      // 128

// ---------------------------------------------------------------------------
// Scratch (device globals; no allocation in kernel_launch)
// ---------------------------------------------------------------------------
__device__ float g_Q  [(size_t)B_DIM * N_DIM * C_DIM];
__device__ float g_K  [(size_t)B_DIM * M_DIM * C_DIM];
__device__ float g_V  [(size_t)B_DIM * M_DIM * C_DIM];
__device__ float g_ATT[(size_t)B_DIM * N_DIM * C_DIM];
__device__ float g_kvp [(size_t)BH * NCHUNK * D_DIM * D_DIM];
__device__ float g_ksp [(size_t)BH * NCHUNK * D_DIM];
__device__ float g_kv  [BH * D_DIM * D_DIM];
__device__ float g_ksum[BH * D_DIM];

// ---------------------------------------------------------------------------
// Helpers
// ---------------------------------------------------------------------------
__device__ __forceinline__ uint32_t tf32_bits(float x) {
    float r;
    asm("cvt.rna.tf32.f32 %0, %1;" : "=f"(r) : "f"(x));
    return __float_as_uint(r);
}
__device__ __forceinline__ void cp16(uint32_t dst, const void* src) {
    asm volatile("cp.async.cg.shared.global [%0], [%1], 16;" :: "r"(dst), "l"(src));
}
__device__ __forceinline__ uint32_t smem_u32(const void* p) {
    uint32_t a;
    asm("{ .reg .u64 t; cvta.to.shared.u64 t, %1; cvt.u32.u64 %0, t; }"
        : "=r"(a) : "l"(p));
    return a;
}
#define CP_COMMIT() asm volatile("cp.async.commit_group;" ::: "memory")

__device__ __forceinline__ void mma_tf32(
    float c[4], const uint32_t a[4], const uint32_t b[2])
{
    asm volatile(
        "mma.sync.aligned.m16n8k8.row.col.f32.tf32.tf32.f32 "
        "{%0,%1,%2,%3}, {%4,%5,%6,%7}, {%8,%9}, {%0,%1,%2,%3};"
        : "+f"(c[0]), "+f"(c[1]), "+f"(c[2]), "+f"(c[3])
        : "r"(a[0]), "r"(a[1]), "r"(a[2]), "r"(a[3]), "r"(b[0]), "r"(b[1]));
}

// ---------------------------------------------------------------------------
// GEMM: C[32768 x 512] = A[32768 x 512] @ W[512 x 512] + bias, optional
// per-head softmax fused into the epilogue (head = 64 consecutive cols).
// mma.sync tf32. Block tile 128x128, BK=16 double-buffered cp.async.
// 128 threads = 4 warps (2m x 2n), warp tile 64x64.
// ---------------------------------------------------------------------------
#define BK      16
#define A_PAD   20      // floats per m-row in smem
#define W_PAD   136     // floats per k-row in smem
#define A_STG   (128 * A_PAD)
#define W_STG   (BK * W_PAD)

template <bool DO_SOFTMAX>
__global__ __launch_bounds__(128, 2) void gemm_mma(
    const float* __restrict__ A, const float* __restrict__ W,
    const float* __restrict__ bias, float* __restrict__ Cw)
{
    __shared__ float sA[2][A_STG];
    __shared__ float sB[2][W_STG];

    const int tid = threadIdx.x;
    const int bx = blockIdx.x;   // 0..3   output col tile (128)
    const int by = blockIdx.y;   // 0..255 output row tile (128)

    const float* Ab = A + (size_t)by * 128 * C_DIM;
    const float* Wb = W + bx * 128;

    const uint32_t sA0 = smem_u32(&sA[0][0]);
    const uint32_t sA1 = smem_u32(&sA[1][0]);
    const uint32_t sB0 = smem_u32(&sB[0][0]);
    const uint32_t sB1 = smem_u32(&sB[1][0]);

    // ---- stage loader: 128 threads, 4 chunks of A + 4 of W each ----
    auto load_stage = [&](int stg) {
        const int buf = stg & 1;
        const int k0 = stg * BK;
        const uint32_t ab = buf ? sA1 : sA0;
        const uint32_t bb = buf ? sB1 : sB0;
#pragma unroll
        for (int q = 0; q < 4; q++) {
            const int c = tid + q * 128;       // 0..511
            const int row = c >> 2;            // 0..127
            const int cc = c & 3;              // 0..3
            cp16(ab + (uint32_t)(row * A_PAD + cc * 4) * 4u,
                 Ab + (size_t)row * C_DIM + k0 + cc * 4);
        }
#pragma unroll
        for (int q = 0; q < 4; q++) {
            const int c = tid + q * 128;       // 0..511
            const int row = c >> 5;            // 0..15
            const int cc = c & 31;             // 0..31
            cp16(bb + (uint32_t)(row * W_PAD + cc * 4) * 4u,
                 Wb + (size_t)(k0 + row) * C_DIM + cc * 4);
        }
        CP_COMMIT();
    };

    const int wid  = tid >> 5;
    const int lane = tid & 31;
    const int wm = (wid >> 1) * 64;   // warp m-offset: 0 / 64
    const int wn = (wid & 1) * 64;    // warp n-offset: 0 / 64 (one head)
    const int g  = lane >> 2;         // group id 0..7
    const int tg = lane & 3;          // thread-in-group

    float acc[4][8][4];               // [m-tile][n-tile][frag]
#pragma unroll
    for (int i = 0; i < 4; i++)
#pragma unroll
        for (int j = 0; j < 8; j++)
#pragma unroll
            for (int t = 0; t < 4; t++) acc[i][j][t] = 0.f;

    load_stage(0);
    load_stage(1);

    const int NS = C_DIM / BK;   // 32
    for (int i = 0; i < NS; i++) {
        if (i < NS - 2) asm volatile("cp.async.wait_group 1;" ::: "memory");
        else            asm volatile("cp.async.wait_group 0;" ::: "memory");
        __syncthreads();

        const float* a_s = sA[i & 1];
        const float* b_s = sB[i & 1];
#pragma unroll
        for (int kk = 0; kk < BK / 8; kk++) {
            const int k0 = kk * 8;
            uint32_t af[4][4];
#pragma unroll
            for (int mt = 0; mt < 4; mt++) {
                const int m = wm + mt * 16 + g;
                af[mt][0] = tf32_bits(a_s[m * A_PAD + k0 + tg]);
                af[mt][1] = tf32_bits(a_s[(m + 8) * A_PAD + k0 + tg]);
                af[mt][2] = tf32_bits(a_s[m * A_PAD + k0 + tg + 4]);
                af[mt][3] = tf32_bits(a_s[(m + 8) * A_PAD + k0 + tg + 4]);
            }
            uint32_t bf[8][2];
#pragma unroll
            for (int nt = 0; nt < 8; nt++) {
                const int n = wn + nt * 8 + g;
                bf[nt][0] = tf32_bits(b_s[(k0 + tg) * W_PAD + n]);
                bf[nt][1] = tf32_bits(b_s[(k0 + tg + 4) * W_PAD + n]);
            }
#pragma unroll
            for (int mt = 0; mt < 4; mt++)
#pragma unroll
                for (int nt = 0; nt < 8; nt++)
                    mma_tf32(acc[mt][nt], af[mt], bf[nt]);
        }
        __syncthreads();
        if (i + 2 < NS) load_stage(i + 2);
    }

    // ---- epilogue: bias (+ optional per-head softmax) + store ----
    float bc[8][2];
#pragma unroll
    for (int nt = 0; nt < 8; nt++) {
        const int col = bx * 128 + wn + nt * 8 + tg * 2;
        bc[nt][0] = __ldg(bias + col);
        bc[nt][1] = __ldg(bias + col + 1);
    }
#pragma unroll
    for (int mt = 0; mt < 4; mt++)
#pragma unroll
        for (int nt = 0; nt < 8; nt++) {
            acc[mt][nt][0] += bc[nt][0];
            acc[mt][nt][1] += bc[nt][1];
            acc[mt][nt][2] += bc[nt][0];
            acc[mt][nt][3] += bc[nt][1];
        }

    if (DO_SOFTMAX) {
        // Warp n-range [wn, wn+64) is exactly one head. Row rA = base+g holds
        // frags 0,1; row rB = base+8+g holds frags 2,3. Each row is spread over
        // the 4 lanes of a tg-group (lanes 4g..4g+3) -> shfl_xor 1,2 reduces.
#pragma unroll
        for (int mt = 0; mt < 4; mt++) {
            float mxA = -1e30f, mxB = -1e30f;
#pragma unroll
            for (int nt = 0; nt < 8; nt++) {
                mxA = fmaxf(mxA, fmaxf(acc[mt][nt][0], acc[mt][nt][1]));
                mxB = fmaxf(mxB, fmaxf(acc[mt][nt][2], acc[mt][nt][3]));
            }
            mxA = fmaxf(mxA, __shfl_xor_sync(~0u, mxA, 1));
            mxA = fmaxf(mxA, __shfl_xor_sync(~0u, mxA, 2));
            mxB = fmaxf(mxB, __shfl_xor_sync(~0u, mxB, 1));
            mxB = fmaxf(mxB, __shfl_xor_sync(~0u, mxB, 2));
            float sA_ = 0.f, sB_ = 0.f;
#pragma unroll
            for (int nt = 0; nt < 8; nt++) {
                acc[mt][nt][0] = __expf(acc[mt][nt][0] - mxA);
                acc[mt][nt][1] = __expf(acc[mt][nt][1] - mxA);
                acc[mt][nt][2] = __expf(acc[mt][nt][2] - mxB);
                acc[mt][nt][3] = __expf(acc[mt][nt][3] - mxB);
                sA_ += acc[mt][nt][0] + acc[mt][nt][1];
                sB_ += acc[mt][nt][2] + acc[mt][nt][3];
            }
            sA_ += __shfl_xor_sync(~0u, sA_, 1);
            sA_ += __shfl_xor_sync(~0u, sA_, 2);
            sB_ += __shfl_xor_sync(~0u, sB_, 1);
            sB_ += __shfl_xor_sync(~0u, sB_, 2);
            const float invA = 1.0f / sA_;
            const float invB = 1.0f / sB_;
#pragma unroll
            for (int nt = 0; nt < 8; nt++) {
                acc[mt][nt][0] *= invA;
                acc[mt][nt][1] *= invA;
                acc[mt][nt][2] *= invB;
                acc[mt][nt][3] *= invB;
            }
        }
    }

#pragma unroll
    for (int nt = 0; nt < 8; nt++) {
        const int col = bx * 128 + wn + nt * 8 + tg * 2;
#pragma unroll
        for (int mt = 0; mt < 4; mt++) {
            const size_t r0 = (size_t)by * 128 + wm + mt * 16 + g;
            *(float2*)(Cw + r0 * C_DIM + col) =
                make_float2(acc[mt][nt][0], acc[mt][nt][1]);
            *(float2*)(Cw + (r0 + 8) * C_DIM + col) =
                make_float2(acc[mt][nt][2], acc[mt][nt][3]);
        }
    }
}

// ---------------------------------------------------------------------------
// kv partials + reduce (deterministic, fp32)
// ---------------------------------------------------------------------------
__global__ __launch_bounds__(256) void kv_partial_k()
{
    const int bh = blockIdx.x, chunk = blockIdx.y;
    const int b = bh >> 3, h = bh & 7;
    __shared__ float Ks[CH][64];
    __shared__ float Vs[CH][64];
    const int tid = threadIdx.x;
    const float* Kb = g_K + ((size_t)b * M_DIM + chunk * CH) * C_DIM + h * D_DIM;
    const float* Vb = g_V + ((size_t)b * M_DIM + chunk * CH) * C_DIM + h * D_DIM;

    for (int i = tid; i < CH * 16; i += 256) {
        int m = i >> 4, c4 = (i & 15) << 2;
        *(float4*)&Ks[m][c4] = *(const float4*)(Kb + (size_t)m * C_DIM + c4);
        *(float4*)&Vs[m][c4] = *(const float4*)(Vb + (size_t)m * C_DIM + c4);
    }
    __syncthreads();

    const int d0 = (tid >> 4) << 2;
    const int e0 = (tid & 15) << 2;
    float acc[4][4] = {};
    for (int m = 0; m < CH; m++) {
        float4 kd = *(const float4*)&Ks[m][d0];
        float4 ve = *(const float4*)&Vs[m][e0];
        float kf[4] = {kd.x, kd.y, kd.z, kd.w};
        float vf[4] = {ve.x, ve.y, ve.z, ve.w};
#pragma unroll
        for (int i = 0; i < 4; i++)
#pragma unroll
            for (int j = 0; j < 4; j++)
                acc[i][j] += kf[i] * vf[j];
    }
    float* dst = g_kvp + ((size_t)bh * NCHUNK + chunk) * (D_DIM * D_DIM);
#pragma unroll
    for (int i = 0; i < 4; i++) {
        float4 o = make_float4(acc[i][0], acc[i][1], acc[i][2], acc[i][3]);
        *(float4*)(dst + (d0 + i) * D_DIM + e0) = o;
    }
    if (tid < 64) {
        float s = 0.f;
        for (int m = 0; m < CH; m++) s += Ks[m][tid];
        g_ksp[((size_t)bh * NCHUNK + chunk) * D_DIM + tid] = s;
    }
}

__global__ __launch_bounds__(256) void kv_reduce_k()
{
    const int bh = blockIdx.x;
    const int i = blockIdx.y * 256 + threadIdx.x;
    const float* src = g_kvp + (size_t)bh * NCHUNK * (D_DIM * D_DIM) + i;
    float s = 0.f;
    for (int c = 0; c < NCHUNK; c++) s += src[(size_t)c * (D_DIM * D_DIM)];
    g_kv[bh * (D_DIM * D_DIM) + i] = s;
    if (blockIdx.y == 0 && threadIdx.x < 64) {
        const float* sp = g_ksp + (size_t)bh * NCHUNK * D_DIM + threadIdx.x;
        float t = 0.f;
        for (int c = 0; c < NCHUNK; c++) t += sp[c * D_DIM];
        g_ksum[bh * D_DIM + threadIdx.x] = t;
    }
}

// ---------------------------------------------------------------------------
// Attention core: ATT = q @ kv / denom + q
// ---------------------------------------------------------------------------
__global__ __launch_bounds__(256) void attn_k()
{
    const int bh = blockIdx.x;
    const int b = bh >> 3, h = bh & 7;
    const int n0 = blockIdx.y * 64;
    __shared__ float kvs[64][64];
    __shared__ float ksums[64];
    __shared__ float qs[64][68];
    const int tid = threadIdx.x;

    {
        const float* kvsrc = g_kv + bh * (D_DIM * D_DIM);
        for (int i = tid; i < 1024; i += 256) {
            int d = i >> 4, c4 = (i & 15) << 2;
            *(float4*)&kvs[d][c4] = *(const float4*)(kvsrc + d * 64 + c4);
        }
        const float* Qb = g_Q + ((size_t)b * N_DIM + n0) * C_DIM + h * D_DIM;
        for (int i = tid; i < 1024; i += 256) {
            int m = i >> 4, c4 = (i & 15) << 2;
            *(float4*)&qs[m][c4] = *(const float4*)(Qb + (size_t)m * C_DIM + c4);
        }
        if (tid < 64) ksums[tid] = g_ksum[bh * D_DIM + tid];
    }
    __syncthreads();

    const int r  = tid >> 2;
    const int e0 = (tid & 3) << 4;

    float denom = 0.f;
#pragma unroll
    for (int d = 0; d < 64; d++) denom += qs[r][d] * ksums[d];
    denom = fmaxf(denom, 1e-6f);
    const float inv = 1.0f / denom;

    float acc[16] = {};
    for (int d = 0; d < 64; d++) {
        float qd = qs[r][d];
#pragma unroll
        for (int j = 0; j < 16; j++) acc[j] += qd * kvs[d][e0 + j];
    }

    float* Ob = g_ATT + ((size_t)b * N_DIM + n0 + r) * C_DIM + h * D_DIM + e0;
#pragma unroll
    for (int j = 0; j < 16; j += 4) {
        float4 o;
        o.x = acc[j + 0] * inv + qs[r][e0 + j + 0];
        o.y = acc[j + 1] * inv + qs[r][e0 + j + 1];
        o.z = acc[j + 2] * inv + qs[r][e0 + j + 2];
        o.w = acc[j + 3] * inv + qs[r][e0 + j + 3];
        *(float4*)(Ob + j) = o;
    }
}

// ---------------------------------------------------------------------------
// Launch
// ---------------------------------------------------------------------------
static float* sym_addr(const void* s)
{
    void* p = nullptr;
    cudaGetSymbolAddress(&p, s);
    return (float*)p;
}

extern "C" void kernel_launch(void* const* d_in, const int* in_sizes, int n_in,
                              void* d_out, int out_size)
{
    const float* x  = (const float*)d_in[0];
    const float* y  = (const float*)d_in[1];
    const float* Wq = (const float*)d_in[2];
    const float* bq = (const float*)d_in[3];
    const float* Wk = (const float*)d_in[4];
    const float* bk = (const float*)d_in[5];
    const float* Wv = (const float*)d_in[6];
    const float* bv = (const float*)d_in[7];
    const float* Wp = (const float*)d_in[8];
    const float* bp = (const float*)d_in[9];
    float* out = (float*)d_out;

    float* Q   = sym_addr(g_Q);
    float* K   = sym_addr(g_K);
    float* V   = sym_addr(g_V);
    float* ATT = sym_addr(g_ATT);

    dim3 ggrid(C_DIM / 128, ROWS / 128);   // (4, 256)

    gemm_mma<true ><<<ggrid, 128>>>(x, Wq, bq, Q);   // Q = softmax(xWq + bq)
    gemm_mma<true ><<<ggrid, 128>>>(y, Wk, bk, K);   // K = softmax(yWk + bk)
    gemm_mma<false><<<ggrid, 128>>>(y, Wv, bv, V);   // V = yWv + bv

    kv_partial_k<<<dim3(BH, NCHUNK), 256>>>();
    kv_reduce_k<<<dim3(BH, 16), 256>>>();

    attn_k<<<dim3(BH, N_DIM / 64), 256>>>();

    gemm_mma<false><<<ggrid, 128>>>(ATT, Wp, bp, out);
}

// round 10
// speedup vs baseline: 3.5683x; 1.4122x over previous
#include <cuda_runtime.h>
#include <cuda_fp16.h>
#include <cstdint>
#include <math.h>

// Problem constants
#define B_DIM 4
#define N_DIM 8192
#define M_DIM 8192
#define C_DIM 512
#define H_DIM 8
#define D_DIM 64
#define BH    (B_DIM * H_DIM)     // 32
#define ROWS  (B_DIM * N_DIM)     // 32768
#define CH      64
#define NCHUNK  (M_DIM / CH)      // 128

// ---------------------------------------------------------------------------
// Scratch (device globals; no allocation in kernel_launch)
// ---------------------------------------------------------------------------
__device__ float  g_Q  [(size_t)B_DIM * N_DIM * C_DIM];
__device__ float  g_K  [(size_t)B_DIM * M_DIM * C_DIM];
__device__ float  g_V  [(size_t)B_DIM * M_DIM * C_DIM];
__device__ __half g_xh [(size_t)B_DIM * N_DIM * C_DIM];
__device__ __half g_yh [(size_t)B_DIM * M_DIM * C_DIM];
__device__ __half g_ATTh[(size_t)B_DIM * N_DIM * C_DIM];
__device__ __half g_Wh [4 * C_DIM * C_DIM];
__device__ float  g_kvp [(size_t)BH * NCHUNK * D_DIM * D_DIM];
__device__ float  g_ksp [(size_t)BH * NCHUNK * D_DIM];
__device__ float  g_kv  [BH * D_DIM * D_DIM];
__device__ float  g_ksum[BH * D_DIM];

// ---------------------------------------------------------------------------
// Helpers
// ---------------------------------------------------------------------------
__device__ __forceinline__ void cp16(uint32_t dst, const void* src) {
    asm volatile("cp.async.cg.shared.global [%0], [%1], 16;" :: "r"(dst), "l"(src));
}
__device__ __forceinline__ uint32_t smem_u32(const void* p) {
    uint32_t a;
    asm("{ .reg .u64 t; cvta.to.shared.u64 t, %1; cvt.u32.u64 %0, t; }"
        : "=r"(a) : "l"(p));
    return a;
}
#define CP_COMMIT() asm volatile("cp.async.commit_group;" ::: "memory")

#define LDSM4(r0, r1, r2, r3, addr) \
    asm volatile("ldmatrix.sync.aligned.m8n8.x4.shared.b16 {%0,%1,%2,%3}, [%4];" \
        : "=r"(r0), "=r"(r1), "=r"(r2), "=r"(r3) : "r"(addr))
#define LDSM4T(r0, r1, r2, r3, addr) \
    asm volatile("ldmatrix.sync.aligned.m8n8.x4.trans.shared.b16 {%0,%1,%2,%3}, [%4];" \
        : "=r"(r0), "=r"(r1), "=r"(r2), "=r"(r3) : "r"(addr))

__device__ __forceinline__ void mma_f16(
    float c[4], const uint32_t a[4], const uint32_t b[2])
{
    asm volatile(
        "mma.sync.aligned.m16n8k16.row.col.f32.f16.f16.f32 "
        "{%0,%1,%2,%3}, {%4,%5,%6,%7}, {%8,%9}, {%0,%1,%2,%3};"
        : "+f"(c[0]), "+f"(c[1]), "+f"(c[2]), "+f"(c[3])
        : "r"(a[0]), "r"(a[1]), "r"(a[2]), "r"(a[3]), "r"(b[0]), "r"(b[1]));
}

// ---------------------------------------------------------------------------
// fp32 -> fp16 conversion pre-pass
// ---------------------------------------------------------------------------
__global__ __launch_bounds__(256) void cvt_half_k(
    const float4* __restrict__ in, __half2* __restrict__ out, int n4)
{
    int i = blockIdx.x * blockDim.x + threadIdx.x;
    const int stride = gridDim.x * blockDim.x;
    for (; i < n4; i += stride) {
        float4 v = in[i];
        out[i * 2]     = __floats2half2_rn(v.x, v.y);
        out[i * 2 + 1] = __floats2half2_rn(v.z, v.w);
    }
}

// ---------------------------------------------------------------------------
// GEMM: C[32768 x 512] = A[32768 x 512] @ W[512 x 512] + bias, optional
// per-head softmax fused in epilogue. fp16 mma.sync m16n8k16 + ldmatrix.
// Block 128x128, BK=32, 3-stage cp.async pipeline (dynamic smem).
// 256 threads = 8 warps (4m x 2n), warp tile 32x64 (one head wide).
// A smem: 128 rows x 40 halves (80B row -> conflict-free ldmatrix).
// B smem: 32 k-rows x 136 halves (272B row -> conflict-free ldmatrix.trans).
// ---------------------------------------------------------------------------
#define BK       32
#define NSTG     (C_DIM / BK)     // 16
#define A_ROWB   80               // bytes per A smem row
#define B_ROWB   272              // bytes per B smem row
#define A_STAGE  (128 * A_ROWB)   // 10240
#define B_STAGE  (BK * B_ROWB)    // 8704
#define GEMM_SMEM (3 * (A_STAGE + B_STAGE))   // 56832

template <bool DO_SOFTMAX>
__global__ __launch_bounds__(256, 2) void gemm_mma(
    const __half* __restrict__ A, const __half* __restrict__ W,
    const float* __restrict__ bias, float* __restrict__ Cw)
{
    extern __shared__ char dsm[];
    const uint32_t aS = smem_u32(dsm);
    const uint32_t bS = aS + 3 * A_STAGE;

    const int tid = threadIdx.x;
    const int bx = blockIdx.x;   // 0..3   output col tile (128)
    const int by = blockIdx.y;   // 0..255 output row tile (128)

    const __half* Ab = A + (size_t)by * 128 * C_DIM;
    const __half* Wb = W + bx * 128;

    // ---- stage loader: 256 threads, 2 A chunks + 2 B chunks each ----
    auto load_stage = [&](int stg) {
        const int buf = stg % 3;
        const int k0 = stg * BK;
        const uint32_t ab = aS + buf * A_STAGE;
        const uint32_t bb = bS + buf * B_STAGE;
#pragma unroll
        for (int q = 0; q < 2; q++) {
            const int c = tid + q * 256;       // 0..511
            const int row = c >> 2;            // 0..127
            const int ch = c & 3;              // k chunk (8 halves)
            cp16(ab + (uint32_t)(row * A_ROWB + ch * 16),
                 Ab + (size_t)row * C_DIM + k0 + ch * 8);
        }
#pragma unroll
        for (int q = 0; q < 2; q++) {
            const int c = tid + q * 256;       // 0..511
            const int row = c >> 4;            // 0..31 (k row)
            const int ch = c & 15;             // n chunk (8 halves)
            cp16(bb + (uint32_t)(row * B_ROWB + ch * 16),
                 Wb + (size_t)(k0 + row) * C_DIM + ch * 8);
        }
        CP_COMMIT();
    };

    const int wid  = tid >> 5;
    const int lane = tid & 31;
    const int wm = (wid >> 1) * 32;   // warp m-offset: 0/32/64/96
    const int wn = (wid & 1) * 64;    // warp n-offset: 0/64 (one head)
    const int g  = lane >> 2;         // group id 0..7
    const int tg = lane & 3;          // thread-in-group

    // ldmatrix per-lane base addresses
    const int l7 = lane & 7;
    const int q1 = (lane >> 3) & 1;   // row-half selector
    const int q2 = lane >> 4;         // chunk selector
    const uint32_t aLane = aS + (uint32_t)((wm + l7 + q1 * 8) * A_ROWB + q2 * 16);
    const uint32_t bLane = bS + (uint32_t)((l7 + q1 * 8) * B_ROWB + q2 * 16 + wn * 2);

    float acc[2][8][4];               // [m-tile(16)][n-tile(8)][frag]
#pragma unroll
    for (int i = 0; i < 2; i++)
#pragma unroll
        for (int j = 0; j < 8; j++)
#pragma unroll
            for (int t = 0; t < 4; t++) acc[i][j][t] = 0.f;

    load_stage(0);
    load_stage(1);

    for (int i = 0; i < NSTG; i++) {
        if (i < NSTG - 1) asm volatile("cp.async.wait_group 1;" ::: "memory");
        else              asm volatile("cp.async.wait_group 0;" ::: "memory");
        __syncthreads();
        if (i + 2 < NSTG) load_stage(i + 2);

        const int buf = i % 3;
        const uint32_t aBuf = aLane + buf * A_STAGE;
        const uint32_t bBuf = bLane + buf * B_STAGE;
#pragma unroll
        for (int kk = 0; kk < 2; kk++) {          // two k16 steps per BK=32
            uint32_t a[2][4];
#pragma unroll
            for (int mt = 0; mt < 2; mt++)
                LDSM4(a[mt][0], a[mt][1], a[mt][2], a[mt][3],
                      aBuf + (uint32_t)(mt * 16 * A_ROWB + kk * 32));
            uint32_t b[8][2];
#pragma unroll
            for (int np = 0; np < 4; np++)
                LDSM4T(b[2 * np][0], b[2 * np][1], b[2 * np + 1][0], b[2 * np + 1][1],
                       bBuf + (uint32_t)(kk * 16 * B_ROWB + np * 32));
#pragma unroll
            for (int mt = 0; mt < 2; mt++)
#pragma unroll
                for (int nt = 0; nt < 8; nt++)
                    mma_f16(acc[mt][nt], a[mt], b[nt]);
        }
    }

    // ---- epilogue: bias (+ optional per-head softmax) + store ----
    float bc[8][2];
#pragma unroll
    for (int nt = 0; nt < 8; nt++) {
        const int col = bx * 128 + wn + nt * 8 + tg * 2;
        bc[nt][0] = __ldg(bias + col);
        bc[nt][1] = __ldg(bias + col + 1);
    }
#pragma unroll
    for (int mt = 0; mt < 2; mt++)
#pragma unroll
        for (int nt = 0; nt < 8; nt++) {
            acc[mt][nt][0] += bc[nt][0];
            acc[mt][nt][1] += bc[nt][1];
            acc[mt][nt][2] += bc[nt][0];
            acc[mt][nt][3] += bc[nt][1];
        }

    if (DO_SOFTMAX) {
        // Warp n-range [wn, wn+64) is exactly one head. Row rA = wm+mt*16+g
        // holds frags 0,1; row rB = +8 holds 2,3; each row spans the 4 lanes
        // of a tg-group -> shfl_xor 1,2 completes the 64-col reduction.
#pragma unroll
        for (int mt = 0; mt < 2; mt++) {
            float mxA = -1e30f, mxB = -1e30f;
#pragma unroll
            for (int nt = 0; nt < 8; nt++) {
                mxA = fmaxf(mxA, fmaxf(acc[mt][nt][0], acc[mt][nt][1]));
                mxB = fmaxf(mxB, fmaxf(acc[mt][nt][2], acc[mt][nt][3]));
            }
            mxA = fmaxf(mxA, __shfl_xor_sync(~0u, mxA, 1));
            mxA = fmaxf(mxA, __shfl_xor_sync(~0u, mxA, 2));
            mxB = fmaxf(mxB, __shfl_xor_sync(~0u, mxB, 1));
            mxB = fmaxf(mxB, __shfl_xor_sync(~0u, mxB, 2));
            float sA_ = 0.f, sB_ = 0.f;
#pragma unroll
            for (int nt = 0; nt < 8; nt++) {
                acc[mt][nt][0] = __expf(acc[mt][nt][0] - mxA);
                acc[mt][nt][1] = __expf(acc[mt][nt][1] - mxA);
                acc[mt][nt][2] = __expf(acc[mt][nt][2] - mxB);
                acc[mt][nt][3] = __expf(acc[mt][nt][3] - mxB);
                sA_ += acc[mt][nt][0] + acc[mt][nt][1];
                sB_ += acc[mt][nt][2] + acc[mt][nt][3];
            }
            sA_ += __shfl_xor_sync(~0u, sA_, 1);
            sA_ += __shfl_xor_sync(~0u, sA_, 2);
            sB_ += __shfl_xor_sync(~0u, sB_, 1);
            sB_ += __shfl_xor_sync(~0u, sB_, 2);
            const float invA = 1.0f / sA_;
            const float invB = 1.0f / sB_;
#pragma unroll
            for (int nt = 0; nt < 8; nt++) {
                acc[mt][nt][0] *= invA;
                acc[mt][nt][1] *= invA;
                acc[mt][nt][2] *= invB;
                acc[mt][nt][3] *= invB;
            }
        }
    }

#pragma unroll
    for (int nt = 0; nt < 8; nt++) {
        const int col = bx * 128 + wn + nt * 8 + tg * 2;
#pragma unroll
        for (int mt = 0; mt < 2; mt++) {
            const size_t r0 = (size_t)by * 128 + wm + mt * 16 + g;
            *(float2*)(Cw + r0 * C_DIM + col) =
                make_float2(acc[mt][nt][0], acc[mt][nt][1]);
            *(float2*)(Cw + (r0 + 8) * C_DIM + col) =
                make_float2(acc[mt][nt][2], acc[mt][nt][3]);
        }
    }
}

// ---------------------------------------------------------------------------
// kv partials + reduce (deterministic, fp32)
// ---------------------------------------------------------------------------
__global__ __launch_bounds__(256) void kv_partial_k()
{
    const int bh = blockIdx.x, chunk = blockIdx.y;
    const int b = bh >> 3, h = bh & 7;
    __shared__ float Ks[CH][64];
    __shared__ float Vs[CH][64];
    const int tid = threadIdx.x;
    const float* Kb = g_K + ((size_t)b * M_DIM + chunk * CH) * C_DIM + h * D_DIM;
    const float* Vb = g_V + ((size_t)b * M_DIM + chunk * CH) * C_DIM + h * D_DIM;

    for (int i = tid; i < CH * 16; i += 256) {
        int m = i >> 4, c4 = (i & 15) << 2;
        *(float4*)&Ks[m][c4] = *(const float4*)(Kb + (size_t)m * C_DIM + c4);
        *(float4*)&Vs[m][c4] = *(const float4*)(Vb + (size_t)m * C_DIM + c4);
    }
    __syncthreads();

    const int d0 = (tid >> 4) << 2;
    const int e0 = (tid & 15) << 2;
    float acc[4][4] = {};
    for (int m = 0; m < CH; m++) {
        float4 kd = *(const float4*)&Ks[m][d0];
        float4 ve = *(const float4*)&Vs[m][e0];
        float kf[4] = {kd.x, kd.y, kd.z, kd.w};
        float vf[4] = {ve.x, ve.y, ve.z, ve.w};
#pragma unroll
        for (int i = 0; i < 4; i++)
#pragma unroll
            for (int j = 0; j < 4; j++)
                acc[i][j] += kf[i] * vf[j];
    }
    float* dst = g_kvp + ((size_t)bh * NCHUNK + chunk) * (D_DIM * D_DIM);
#pragma unroll
    for (int i = 0; i < 4; i++) {
        float4 o = make_float4(acc[i][0], acc[i][1], acc[i][2], acc[i][3]);
        *(float4*)(dst + (d0 + i) * D_DIM + e0) = o;
    }
    if (tid < 64) {
        float s = 0.f;
        for (int m = 0; m < CH; m++) s += Ks[m][tid];
        g_ksp[((size_t)bh * NCHUNK + chunk) * D_DIM + tid] = s;
    }
}

__global__ __launch_bounds__(256) void kv_reduce_k()
{
    const int bh = blockIdx.x;
    const int i = blockIdx.y * 256 + threadIdx.x;
    const float* src = g_kvp + (size_t)bh * NCHUNK * (D_DIM * D_DIM) + i;
    float s = 0.f;
    for (int c = 0; c < NCHUNK; c++) s += src[(size_t)c * (D_DIM * D_DIM)];
    g_kv[bh * (D_DIM * D_DIM) + i] = s;
    if (blockIdx.y == 0 && threadIdx.x < 64) {
        const float* sp = g_ksp + (size_t)bh * NCHUNK * D_DIM + threadIdx.x;
        float t = 0.f;
        for (int c = 0; c < NCHUNK; c++) t += sp[c * D_DIM];
        g_ksum[bh * D_DIM + threadIdx.x] = t;
    }
}

// ---------------------------------------------------------------------------
// Attention core: ATT = q @ kv / denom + q   (emits fp16 for final GEMM)
// ---------------------------------------------------------------------------
__global__ __launch_bounds__(256) void attn_k()
{
    const int bh = blockIdx.x;
    const int b = bh >> 3, h = bh & 7;
    const int n0 = blockIdx.y * 64;
    __shared__ float kvs[64][64];
    __shared__ float ksums[64];
    __shared__ float qs[64][68];
    const int tid = threadIdx.x;

    {
        const float* kvsrc = g_kv + bh * (D_DIM * D_DIM);
        for (int i = tid; i < 1024; i += 256) {
            int d = i >> 4, c4 = (i & 15) << 2;
            *(float4*)&kvs[d][c4] = *(const float4*)(kvsrc + d * 64 + c4);
        }
        const float* Qb = g_Q + ((size_t)b * N_DIM + n0) * C_DIM + h * D_DIM;
        for (int i = tid; i < 1024; i += 256) {
            int m = i >> 4, c4 = (i & 15) << 2;
            *(float4*)&qs[m][c4] = *(const float4*)(Qb + (size_t)m * C_DIM + c4);
        }
        if (tid < 64) ksums[tid] = g_ksum[bh * D_DIM + tid];
    }
    __syncthreads();

    const int r  = tid >> 2;
    const int e0 = (tid & 3) << 4;

    float denom = 0.f;
#pragma unroll
    for (int d = 0; d < 64; d++) denom += qs[r][d] * ksums[d];
    denom = fmaxf(denom, 1e-6f);
    const float inv = 1.0f / denom;

    float acc[16] = {};
    for (int d = 0; d < 64; d++) {
        float qd = qs[r][d];
#pragma unroll
        for (int j = 0; j < 16; j++) acc[j] += qd * kvs[d][e0 + j];
    }

    __half* Ob = g_ATTh + ((size_t)b * N_DIM + n0 + r) * C_DIM + h * D_DIM + e0;
#pragma unroll
    for (int j = 0; j < 16; j += 2) {
        float v0 = acc[j + 0] * inv + qs[r][e0 + j + 0];
        float v1 = acc[j + 1] * inv + qs[r][e0 + j + 1];
        *(__half2*)(Ob + j) = __floats2half2_rn(v0, v1);
    }
}

// ---------------------------------------------------------------------------
// Launch
// ---------------------------------------------------------------------------
template <typename T>
static T* sym_addr(const void* s)
{
    void* p = nullptr;
    cudaGetSymbolAddress(&p, s);
    return (T*)p;
}

extern "C" void kernel_launch(void* const* d_in, const int* in_sizes, int n_in,
                              void* d_out, int out_size)
{
    const float* x  = (const float*)d_in[0];
    const float* y  = (const float*)d_in[1];
    const float* Wq = (const float*)d_in[2];
    const float* bq = (const float*)d_in[3];
    const float* Wk = (const float*)d_in[4];
    const float* bk = (const float*)d_in[5];
    const float* Wv = (const float*)d_in[6];
    const float* bv = (const float*)d_in[7];
    const float* Wp = (const float*)d_in[8];
    const float* bp = (const float*)d_in[9];
    float* out = (float*)d_out;

    float*  Q    = sym_addr<float>(g_Q);
    float*  K    = sym_addr<float>(g_K);
    float*  V    = sym_addr<float>(g_V);
    __half* xh   = sym_addr<__half>(g_xh);
    __half* yh   = sym_addr<__half>(g_yh);
    __half* ATTh = sym_addr<__half>(g_ATTh);
    __half* Wh   = sym_addr<__half>(g_Wh);

    cudaFuncSetAttribute(gemm_mma<true>,
                         cudaFuncAttributeMaxDynamicSharedMemorySize, GEMM_SMEM);
    cudaFuncSetAttribute(gemm_mma<false>,
                         cudaFuncAttributeMaxDynamicSharedMemorySize, GEMM_SMEM);

    // fp16 conversion pre-pass
    const int n4 = (int)((size_t)ROWS * C_DIM / 4);
    const int w4 = C_DIM * C_DIM / 4;
    cvt_half_k<<<4096, 256>>>((const float4*)x, (__half2*)xh, n4);
    cvt_half_k<<<4096, 256>>>((const float4*)y, (__half2*)yh, n4);
    cvt_half_k<<<256, 256>>>((const float4*)Wq, (__half2*)(Wh + 0 * C_DIM * C_DIM), w4);
    cvt_half_k<<<256, 256>>>((const float4*)Wk, (__half2*)(Wh + 1 * C_DIM * C_DIM), w4);
    cvt_half_k<<<256, 256>>>((const float4*)Wv, (__half2*)(Wh + 2 * C_DIM * C_DIM), w4);
    cvt_half_k<<<256, 256>>>((const float4*)Wp, (__half2*)(Wh + 3 * C_DIM * C_DIM), w4);

    dim3 ggrid(C_DIM / 128, ROWS / 128);   // (4, 256)

    gemm_mma<true ><<<ggrid, 256, GEMM_SMEM>>>(xh, Wh + 0 * C_DIM * C_DIM, bq, Q);
    gemm_mma<true ><<<ggrid, 256, GEMM_SMEM>>>(yh, Wh + 1 * C_DIM * C_DIM, bk, K);
    gemm_mma<false><<<ggrid, 256, GEMM_SMEM>>>(yh, Wh + 2 * C_DIM * C_DIM, bv, V);

    kv_partial_k<<<dim3(BH, NCHUNK), 256>>>();
    kv_reduce_k<<<dim3(BH, 16), 256>>>();

    attn_k<<<dim3(BH, N_DIM / 64), 256>>>();

    gemm_mma<false><<<ggrid, 256, GEMM_SMEM>>>(ATTh, Wh + 3 * C_DIM * C_DIM, bp, out);
}

// round 12
// speedup vs baseline: 3.8866x; 1.0892x over previous
#include <cuda_runtime.h>
#include <cuda_fp16.h>
#include <cstdint>
#include <math.h>

// Problem constants
#define B_DIM 4
#define N_DIM 8192
#define M_DIM 8192
#define C_DIM 512
#define H_DIM 8
#define D_DIM 64
#define BH    (B_DIM * H_DIM)     // 32
#define ROWS  (B_DIM * N_DIM)     // 32768

// kv chunking
#define CH2   512
#define NCH2  (M_DIM / CH2)       // 16

// ---------------------------------------------------------------------------
// Scratch (device globals; no allocation in kernel_launch)
// ---------------------------------------------------------------------------
__device__ __half g_Qh [(size_t)B_DIM * N_DIM * C_DIM];
__device__ __half g_Kh [(size_t)B_DIM * M_DIM * C_DIM];
__device__ __half g_Vh [(size_t)B_DIM * M_DIM * C_DIM];
__device__ __half g_xh [(size_t)B_DIM * N_DIM * C_DIM];
__device__ __half g_yh [(size_t)B_DIM * M_DIM * C_DIM];
__device__ __half g_ATTh[(size_t)B_DIM * N_DIM * C_DIM];
__device__ __half g_Wh [4 * C_DIM * C_DIM];
__device__ float  g_kvp [(size_t)BH * NCH2 * D_DIM * D_DIM];
__device__ float  g_ksp [(size_t)BH * NCH2 * D_DIM];
__device__ float  g_kv  [BH * D_DIM * D_DIM];
__device__ float  g_ksum[BH * D_DIM];

// ---------------------------------------------------------------------------
// Helpers
// ---------------------------------------------------------------------------
__device__ __forceinline__ void cp16(uint32_t dst, const void* src) {
    asm volatile("cp.async.cg.shared.global [%0], [%1], 16;" :: "r"(dst), "l"(src));
}
__device__ __forceinline__ uint32_t smem_u32(const void* p) {
    uint32_t a;
    asm("{ .reg .u64 t; cvta.to.shared.u64 t, %1; cvt.u32.u64 %0, t; }"
        : "=r"(a) : "l"(p));
    return a;
}
#define CP_COMMIT() asm volatile("cp.async.commit_group;" ::: "memory")

#define LDSM4(r0, r1, r2, r3, addr) \
    asm volatile("ldmatrix.sync.aligned.m8n8.x4.shared.b16 {%0,%1,%2,%3}, [%4];" \
        : "=r"(r0), "=r"(r1), "=r"(r2), "=r"(r3) : "r"(addr))
#define LDSM4T(r0, r1, r2, r3, addr) \
    asm volatile("ldmatrix.sync.aligned.m8n8.x4.trans.shared.b16 {%0,%1,%2,%3}, [%4];" \
        : "=r"(r0), "=r"(r1), "=r"(r2), "=r"(r3) : "r"(addr))

__device__ __forceinline__ void mma_f16(
    float c[4], const uint32_t a[4], const uint32_t b[2])
{
    asm volatile(
        "mma.sync.aligned.m16n8k16.row.col.f32.f16.f16.f32 "
        "{%0,%1,%2,%3}, {%4,%5,%6,%7}, {%8,%9}, {%0,%1,%2,%3};"
        : "+f"(c[0]), "+f"(c[1]), "+f"(c[2]), "+f"(c[3])
        : "r"(a[0]), "r"(a[1]), "r"(a[2]), "r"(a[3]), "r"(b[0]), "r"(b[1]));
}

__device__ __forceinline__ void store_pair(float* p, float a, float b) {
    *(float2*)p = make_float2(a, b);
}
__device__ __forceinline__ void store_pair(__half* p, float a, float b) {
    *(__half2*)p = __floats2half2_rn(a, b);
}

// ---------------------------------------------------------------------------
// fp32 -> fp16 conversion pre-passes
// ---------------------------------------------------------------------------
__global__ __launch_bounds__(256) void cvt_half_k(
    const float4* __restrict__ in, __half2* __restrict__ out, int n4)
{
    int i = blockIdx.x * blockDim.x + threadIdx.x;
    const int stride = gridDim.x * blockDim.x;
    for (; i < n4; i += stride) {
        float4 v = in[i];
        out[i * 2]     = __floats2half2_rn(v.x, v.y);
        out[i * 2 + 1] = __floats2half2_rn(v.z, v.w);
    }
}

// All 4 weight matrices in one launch (blockIdx.y selects)
__global__ __launch_bounds__(256) void cvt_w4_k(
    const float4* __restrict__ w0, const float4* __restrict__ w1,
    const float4* __restrict__ w2, const float4* __restrict__ w3,
    __half2* __restrict__ out)
{
    const float4* srcs[4] = {w0, w1, w2, w3};
    const float4* in = srcs[blockIdx.y];
    __half2* o = out + (size_t)blockIdx.y * (C_DIM * C_DIM / 2);
    const int n4 = C_DIM * C_DIM / 4;
    for (int i = blockIdx.x * 256 + threadIdx.x; i < n4; i += gridDim.x * 256) {
        float4 v = in[i];
        o[i * 2]     = __floats2half2_rn(v.x, v.y);
        o[i * 2 + 1] = __floats2half2_rn(v.z, v.w);
    }
}

// ---------------------------------------------------------------------------
// GEMM: C[32768 x 512] = A[32768 x 512] @ W[512 x 512] + bias, optional
// per-head softmax fused in epilogue. fp16 mma.sync m16n8k16 + ldmatrix.
// Block 128x128, BK=32, 3-stage cp.async pipeline. Output float or half.
// ---------------------------------------------------------------------------
#define BK       32
#define NSTG     (C_DIM / BK)     // 16
#define A_ROWB   80
#define B_ROWB   272
#define A_STAGE  (128 * A_ROWB)   // 10240
#define B_STAGE  (BK * B_ROWB)    // 8704
#define GEMM_SMEM (3 * (A_STAGE + B_STAGE))   // 56832

template <bool DO_SOFTMAX, typename TO>
__global__ __launch_bounds__(256, 2) void gemm_mma(
    const __half* __restrict__ A, const __half* __restrict__ W,
    const float* __restrict__ bias, TO* __restrict__ Cw)
{
    extern __shared__ char dsm[];
    const uint32_t aS = smem_u32(dsm);
    const uint32_t bS = aS + 3 * A_STAGE;

    const int tid = threadIdx.x;
    const int bx = blockIdx.x;
    const int by = blockIdx.y;

    const __half* Ab = A + (size_t)by * 128 * C_DIM;
    const __half* Wb = W + bx * 128;

    auto load_stage = [&](int stg) {
        const int buf = stg % 3;
        const int k0 = stg * BK;
        const uint32_t ab = aS + buf * A_STAGE;
        const uint32_t bb = bS + buf * B_STAGE;
#pragma unroll
        for (int q = 0; q < 2; q++) {
            const int c = tid + q * 256;
            const int row = c >> 2;
            const int ch = c & 3;
            cp16(ab + (uint32_t)(row * A_ROWB + ch * 16),
                 Ab + (size_t)row * C_DIM + k0 + ch * 8);
        }
#pragma unroll
        for (int q = 0; q < 2; q++) {
            const int c = tid + q * 256;
            const int row = c >> 4;
            const int ch = c & 15;
            cp16(bb + (uint32_t)(row * B_ROWB + ch * 16),
                 Wb + (size_t)(k0 + row) * C_DIM + ch * 8);
        }
        CP_COMMIT();
    };

    const int wid  = tid >> 5;
    const int lane = tid & 31;
    const int wm = (wid >> 1) * 32;
    const int wn = (wid & 1) * 64;
    const int g  = lane >> 2;
    const int tg = lane & 3;

    const int l7 = lane & 7;
    const int q1 = (lane >> 3) & 1;
    const int q2 = lane >> 4;
    const uint32_t aLane = aS + (uint32_t)((wm + l7 + q1 * 8) * A_ROWB + q2 * 16);
    const uint32_t bLane = bS + (uint32_t)((l7 + q1 * 8) * B_ROWB + q2 * 16 + wn * 2);

    float acc[2][8][4];
#pragma unroll
    for (int i = 0; i < 2; i++)
#pragma unroll
        for (int j = 0; j < 8; j++)
#pragma unroll
            for (int t = 0; t < 4; t++) acc[i][j][t] = 0.f;

    load_stage(0);
    load_stage(1);

    for (int i = 0; i < NSTG; i++) {
        if (i < NSTG - 1) asm volatile("cp.async.wait_group 1;" ::: "memory");
        else              asm volatile("cp.async.wait_group 0;" ::: "memory");
        __syncthreads();
        if (i + 2 < NSTG) load_stage(i + 2);

        const int buf = i % 3;
        const uint32_t aBuf = aLane + buf * A_STAGE;
        const uint32_t bBuf = bLane + buf * B_STAGE;
#pragma unroll
        for (int kk = 0; kk < 2; kk++) {
            uint32_t a[2][4];
#pragma unroll
            for (int mt = 0; mt < 2; mt++)
                LDSM4(a[mt][0], a[mt][1], a[mt][2], a[mt][3],
                      aBuf + (uint32_t)(mt * 16 * A_ROWB + kk * 32));
            uint32_t b[8][2];
#pragma unroll
            for (int np = 0; np < 4; np++)
                LDSM4T(b[2 * np][0], b[2 * np][1], b[2 * np + 1][0], b[2 * np + 1][1],
                       bBuf + (uint32_t)(kk * 16 * B_ROWB + np * 32));
#pragma unroll
            for (int mt = 0; mt < 2; mt++)
#pragma unroll
                for (int nt = 0; nt < 8; nt++)
                    mma_f16(acc[mt][nt], a[mt], b[nt]);
        }
    }

    // ---- epilogue: bias (+ optional per-head softmax) + store ----
    float bc[8][2];
#pragma unroll
    for (int nt = 0; nt < 8; nt++) {
        const int col = bx * 128 + wn + nt * 8 + tg * 2;
        bc[nt][0] = __ldg(bias + col);
        bc[nt][1] = __ldg(bias + col + 1);
    }
#pragma unroll
    for (int mt = 0; mt < 2; mt++)
#pragma unroll
        for (int nt = 0; nt < 8; nt++) {
            acc[mt][nt][0] += bc[nt][0];
            acc[mt][nt][1] += bc[nt][1];
            acc[mt][nt][2] += bc[nt][0];
            acc[mt][nt][3] += bc[nt][1];
        }

    if (DO_SOFTMAX) {
#pragma unroll
        for (int mt = 0; mt < 2; mt++) {
            float mxA = -1e30f, mxB = -1e30f;
#pragma unroll
            for (int nt = 0; nt < 8; nt++) {
                mxA = fmaxf(mxA, fmaxf(acc[mt][nt][0], acc[mt][nt][1]));
                mxB = fmaxf(mxB, fmaxf(acc[mt][nt][2], acc[mt][nt][3]));
            }
            mxA = fmaxf(mxA, __shfl_xor_sync(~0u, mxA, 1));
            mxA = fmaxf(mxA, __shfl_xor_sync(~0u, mxA, 2));
            mxB = fmaxf(mxB, __shfl_xor_sync(~0u, mxB, 1));
            mxB = fmaxf(mxB, __shfl_xor_sync(~0u, mxB, 2));
            float sA_ = 0.f, sB_ = 0.f;
#pragma unroll
            for (int nt = 0; nt < 8; nt++) {
                acc[mt][nt][0] = __expf(acc[mt][nt][0] - mxA);
                acc[mt][nt][1] = __expf(acc[mt][nt][1] - mxA);
                acc[mt][nt][2] = __expf(acc[mt][nt][2] - mxB);
                acc[mt][nt][3] = __expf(acc[mt][nt][3] - mxB);
                sA_ += acc[mt][nt][0] + acc[mt][nt][1];
                sB_ += acc[mt][nt][2] + acc[mt][nt][3];
            }
            sA_ += __shfl_xor_sync(~0u, sA_, 1);
            sA_ += __shfl_xor_sync(~0u, sA_, 2);
            sB_ += __shfl_xor_sync(~0u, sB_, 1);
            sB_ += __shfl_xor_sync(~0u, sB_, 2);
            const float invA = 1.0f / sA_;
            const float invB = 1.0f / sB_;
#pragma unroll
            for (int nt = 0; nt < 8; nt++) {
                acc[mt][nt][0] *= invA;
                acc[mt][nt][1] *= invA;
                acc[mt][nt][2] *= invB;
                acc[mt][nt][3] *= invB;
            }
        }
    }

#pragma unroll
    for (int nt = 0; nt < 8; nt++) {
        const int col = bx * 128 + wn + nt * 8 + tg * 2;
#pragma unroll
        for (int mt = 0; mt < 2; mt++) {
            const size_t r0 = (size_t)by * 128 + wm + mt * 16 + g;
            store_pair(Cw + r0 * C_DIM + col, acc[mt][nt][0], acc[mt][nt][1]);
            store_pair(Cw + (r0 + 8) * C_DIM + col, acc[mt][nt][2], acc[mt][nt][3]);
        }
    }
}

// ---------------------------------------------------------------------------
// kv partials with fp16 mma: per (bh, chunk of 512 rows) accumulate K^T V
// (64x64 fp32) + column sums of K. Double-buffered 128-row slabs.
// Ks/Vs smem rows padded to 144B -> conflict-free ldmatrix.trans.
// ---------------------------------------------------------------------------
#define KV_PITCHB 144
#define KV_SLABB  (128 * KV_PITCHB)      // 18432
#define KV_SMEM   (2 * 2 * KV_SLABB)     // 73728

__global__ __launch_bounds__(256) void kv_partial_k()
{
    extern __shared__ char dsm[];
    const uint32_t sbase = smem_u32(dsm);
    const int bh = blockIdx.x, chunk = blockIdx.y;
    const int b = bh >> 3, h = bh & 7;
    const int tid = threadIdx.x;
    const __half* Kb = g_Kh + ((size_t)b * M_DIM + chunk * CH2) * C_DIM + h * D_DIM;
    const __half* Vb = g_Vh + ((size_t)b * M_DIM + chunk * CH2) * C_DIM + h * D_DIM;

    auto load_slab = [&](int s) {
        const int buf = s & 1;
        const uint32_t kd = sbase + buf * (2 * KV_SLABB);
        const uint32_t vd = kd + KV_SLABB;
        const int m0 = s * 128;
#pragma unroll
        for (int q = 0; q < 4; q++) {
            const int c = tid + q * 256;       // 0..1023
            const int row = c >> 3, ch = c & 7;
            cp16(kd + (uint32_t)(row * KV_PITCHB + ch * 16),
                 Kb + (size_t)(m0 + row) * C_DIM + ch * 8);
            cp16(vd + (uint32_t)(row * KV_PITCHB + ch * 16),
                 Vb + (size_t)(m0 + row) * C_DIM + ch * 8);
        }
        CP_COMMIT();
    };

    const int wid = tid >> 5, lane = tid & 31;
    const int wd = wid >> 2, we = wid & 3;   // d-tile 0..1, e-tile 0..3
    const int d0 = wd * 32, e0 = we * 16;
    const int g = lane >> 2, tg = lane & 3;
    const int l7 = lane & 7, q1 = (lane >> 3) & 1, q2 = lane >> 4;

    float acc[2][2][4] = {};

    load_slab(0);
    load_slab(1);

    const int NSLAB = CH2 / 128;   // 4
    for (int s = 0; s < NSLAB; s++) {
        if (s < NSLAB - 1) asm volatile("cp.async.wait_group 1;" ::: "memory");
        else               asm volatile("cp.async.wait_group 0;" ::: "memory");
        __syncthreads();
        const int buf = s & 1;
        const uint32_t kS = sbase + buf * (2 * KV_SLABB);
        const uint32_t vS = kS + KV_SLABB;
#pragma unroll
        for (int kk = 0; kk < 8; kk++) {
            const int k0 = kk * 16;
            uint32_t a[2][4];
#pragma unroll
            for (int mt = 0; mt < 2; mt++) {
                const uint32_t addr = kS + (uint32_t)((k0 + l7 + q2 * 8) * KV_PITCHB
                                     + (d0 + mt * 16 + q1 * 8) * 2);
                LDSM4T(a[mt][0], a[mt][1], a[mt][2], a[mt][3], addr);
            }
            uint32_t bfr[2][2];
            {
                const uint32_t addr = vS + (uint32_t)((k0 + l7 + q1 * 8) * KV_PITCHB
                                     + (e0 + q2 * 8) * 2);
                LDSM4T(bfr[0][0], bfr[0][1], bfr[1][0], bfr[1][1], addr);
            }
#pragma unroll
            for (int mt = 0; mt < 2; mt++)
#pragma unroll
                for (int nt = 0; nt < 2; nt++)
                    mma_f16(acc[mt][nt], a[mt], bfr[nt]);
        }
        __syncthreads();
        if (s + 2 < NSLAB) load_slab(s + 2);
    }

    float* dst = g_kvp + ((size_t)bh * NCH2 + chunk) * (D_DIM * D_DIM);
#pragma unroll
    for (int mt = 0; mt < 2; mt++)
#pragma unroll
        for (int nt = 0; nt < 2; nt++) {
            const int d = d0 + mt * 16 + g;
            const int e = e0 + nt * 8 + tg * 2;
            *(float2*)(dst + d * 64 + e)       = make_float2(acc[mt][nt][0], acc[mt][nt][1]);
            *(float2*)(dst + (d + 8) * 64 + e) = make_float2(acc[mt][nt][2], acc[mt][nt][3]);
        }

    // ksum partial: column sums of K over this chunk (global reads, coalesced)
    if (tid < 64) {
        float ssum = 0.f;
        const __half* kp = Kb + tid;
#pragma unroll 8
        for (int m = 0; m < CH2; m++)
            ssum += __half2float(kp[(size_t)m * C_DIM]);
        g_ksp[((size_t)bh * NCH2 + chunk) * D_DIM + tid] = ssum;
    }
}

__global__ __launch_bounds__(256) void kv_reduce_k()
{
    const int bh = blockIdx.x;
    const int i = blockIdx.y * 256 + threadIdx.x;   // 0..4095
    const float* src = g_kvp + (size_t)bh * NCH2 * (D_DIM * D_DIM) + i;
    float s = 0.f;
#pragma unroll
    for (int c = 0; c < NCH2; c++) s += src[(size_t)c * (D_DIM * D_DIM)];
    g_kv[bh * (D_DIM * D_DIM) + i] = s;
    if (blockIdx.y == 0 && threadIdx.x < 64) {
        const float* sp = g_ksp + (size_t)bh * NCH2 * D_DIM + threadIdx.x;
        float t = 0.f;
#pragma unroll
        for (int c = 0; c < NCH2; c++) t += sp[c * D_DIM];
        g_ksum[bh * D_DIM + threadIdx.x] = t;
    }
}

// ---------------------------------------------------------------------------
// Attention core: ATT = q @ kv / denom + q   (fp16 in, fp16 out)
// ---------------------------------------------------------------------------
__global__ __launch_bounds__(256) void attn_k()
{
    const int bh = blockIdx.x;
    const int b = bh >> 3, h = bh & 7;
    const int n0 = blockIdx.y * 64;
    __shared__ float kvs[64][64];
    __shared__ float ksums[64];
    __shared__ float qs[64][68];
    const int tid = threadIdx.x;

    {
        const float* kvsrc = g_kv + bh * (D_DIM * D_DIM);
        for (int i = tid; i < 1024; i += 256) {
            int d = i >> 4, c4 = (i & 15) << 2;
            *(float4*)&kvs[d][c4] = *(const float4*)(kvsrc + d * 64 + c4);
        }
        const __half* Qb = g_Qh + ((size_t)b * N_DIM + n0) * C_DIM + h * D_DIM;
        for (int i = tid; i < 1024; i += 256) {
            int m = i >> 4, c4 = (i & 15) << 2;
            uint2 raw = *(const uint2*)(Qb + (size_t)m * C_DIM + c4);
            float2 f0 = __half22float2(*(__half2*)&raw.x);
            float2 f1 = __half22float2(*(__half2*)&raw.y);
            qs[m][c4] = f0.x; qs[m][c4 + 1] = f0.y;
            qs[m][c4 + 2] = f1.x; qs[m][c4 + 3] = f1.y;
        }
        if (tid < 64) ksums[tid] = g_ksum[bh * D_DIM + tid];
    }
    __syncthreads();

    const int r  = tid >> 2;
    const int e0 = (tid & 3) << 4;

    float denom = 0.f;
#pragma unroll
    for (int d = 0; d < 64; d++) denom += qs[r][d] * ksums[d];
    denom = fmaxf(denom, 1e-6f);
    const float inv = 1.0f / denom;

    float acc[16] = {};
    for (int d = 0; d < 64; d++) {
        float qd = qs[r][d];
#pragma unroll
        for (int j = 0; j < 16; j++) acc[j] += qd * kvs[d][e0 + j];
    }

    __half* Ob = g_ATTh + ((size_t)b * N_DIM + n0 + r) * C_DIM + h * D_DIM + e0;
#pragma unroll
    for (int j = 0; j < 16; j += 2) {
        float v0 = acc[j + 0] * inv + qs[r][e0 + j + 0];
        float v1 = acc[j + 1] * inv + qs[r][e0 + j + 1];
        *(__half2*)(Ob + j) = __floats2half2_rn(v0, v1);
    }
}

// ---------------------------------------------------------------------------
// Launch
// ---------------------------------------------------------------------------
template <typename T>
static T* sym_addr(const void* s)
{
    void* p = nullptr;
    cudaGetSymbolAddress(&p, s);
    return (T*)p;
}

extern "C" void kernel_launch(void* const* d_in, const int* in_sizes, int n_in,
                              void* d_out, int out_size)
{
    const float* x  = (const float*)d_in[0];
    const float* y  = (const float*)d_in[1];
    const float* Wq = (const float*)d_in[2];
    const float* bq = (const float*)d_in[3];
    const float* Wk = (const float*)d_in[4];
    const float* bk = (const float*)d_in[5];
    const float* Wv = (const float*)d_in[6];
    const float* bv = (const float*)d_in[7];
    const float* Wp = (const float*)d_in[8];
    const float* bp = (const float*)d_in[9];
    float* out = (float*)d_out;

    __half* Qh   = sym_addr<__half>(g_Qh);
    __half* Kh   = sym_addr<__half>(g_Kh);
    __half* Vh   = sym_addr<__half>(g_Vh);
    __half* xh   = sym_addr<__half>(g_xh);
    __half* yh   = sym_addr<__half>(g_yh);
    __half* ATTh = sym_addr<__half>(g_ATTh);
    __half* Wh   = sym_addr<__half>(g_Wh);

    cudaFuncSetAttribute((const void*)gemm_mma<true, __half>,
                         cudaFuncAttributeMaxDynamicSharedMemorySize, GEMM_SMEM);
    cudaFuncSetAttribute((const void*)gemm_mma<false, __half>,
                         cudaFuncAttributeMaxDynamicSharedMemorySize, GEMM_SMEM);
    cudaFuncSetAttribute((const void*)gemm_mma<false, float>,
                         cudaFuncAttributeMaxDynamicSharedMemorySize, GEMM_SMEM);
    cudaFuncSetAttribute((const void*)kv_partial_k,
                         cudaFuncAttributeMaxDynamicSharedMemorySize, KV_SMEM);

    // fp16 conversion pre-passes (3 launches)
    const int n4 = (int)((size_t)ROWS * C_DIM / 4);
    cvt_half_k<<<4096, 256>>>((const float4*)x, (__half2*)xh, n4);
    cvt_half_k<<<4096, 256>>>((const float4*)y, (__half2*)yh, n4);
    cvt_w4_k<<<dim3(64, 4), 256>>>((const float4*)Wq, (const float4*)Wk,
                                   (const float4*)Wv, (const float4*)Wp,
                                   (__half2*)Wh);

    dim3 ggrid(C_DIM / 128, ROWS / 128);   // (4, 256)

    gemm_mma<true,  __half><<<ggrid, 256, GEMM_SMEM>>>(xh, Wh + 0 * C_DIM * C_DIM, bq, Qh);
    gemm_mma<true,  __half><<<ggrid, 256, GEMM_SMEM>>>(yh, Wh + 1 * C_DIM * C_DIM, bk, Kh);
    gemm_mma<false, __half><<<ggrid, 256, GEMM_SMEM>>>(yh, Wh + 2 * C_DIM * C_DIM, bv, Vh);

    kv_partial_k<<<dim3(BH, NCH2), 256, KV_SMEM>>>();
    kv_reduce_k<<<dim3(BH, 16), 256>>>();

    attn_k<<<dim3(BH, N_DIM / 64), 256>>>();

    gemm_mma<false, float><<<ggrid, 256, GEMM_SMEM>>>(ATTh, Wh + 3 * C_DIM * C_DIM, bp, out);
}